// round 9
// baseline (speedup 1.0000x reference)
#include <cuda_runtime.h>
#include <math.h>

#define SS 7
#define NPTS 49
#define CCH 256
#define CSPLIT 2
#define CPER (CCH / CSPLIT)

__device__ __forceinline__ float sel4(float4 f, int i) {
    return i == 0 ? f.x : (i == 1 ? f.y : (i == 2 ? f.z : f.w));
}

__global__ __launch_bounds__(256) void oriented_roi_align_kernel(
    const float* __restrict__ f0, const float* __restrict__ f1,
    const float* __restrict__ f2, const float* __restrict__ f3,
    const float* __restrict__ rois, const int* __restrict__ levels,
    float* __restrict__ out, int N)
{
    const int roi  = blockIdx.x >> 1;
    const int half = blockIdx.x & 1;
    const int bb   = roi / N;
    const int tid  = threadIdx.x;

    __shared__ float s_w00[NPTS], s_w01[NPTS], s_w10[NPTS], s_w11[NPTS];
    __shared__ int   s_o00[NPTS], s_dx[NPTS], s_dyw[NPTS];

    const int lvl = __ldg(levels + roi);
    int H; float scale; const float* fbase;
    switch (lvl) {
        case 0:  H = 256; scale = 0.25f;     fbase = f0; break;
        case 1:  H = 128; scale = 0.125f;    fbase = f1; break;
        case 2:  H = 64;  scale = 0.0625f;   fbase = f2; break;
        default: H = 32;  scale = 0.03125f;  fbase = f3; break;
    }
    const int HW = H * H;
    const float* base = fbase + (size_t)bb * CCH * HW;
    float* op = out + (size_t)roi * CCH * NPTS;

    if (tid < NPTS) {
        const float* r = rois + (size_t)roi * 6;
        const float x = r[0], y = r[1], w = r[2], h = r[3], a = r[4], b = r[5];

        // ---- parallelogram -> rectangle (matches reference) ----
        const float d1 = sqrtf(4.f * a * a + h * h);
        const float d2 = sqrtf(w * w + 4.f * b * b);
        const float eps = 1e-6f;
        float V0x, V0y, V1x, V1y, V2x, V2y;
        if (d1 > d2) {
            const float sA = d1 / (d2 + eps);
            V0x = x + a;          V0y = y + 0.5f * h;
            V1x = (x + 0.5f * w) + (sA - 1.f) * (0.5f * w);
            V1y = (y + b)        + (sA - 1.f) * b;
            V2x = x - a;          V2y = y - 0.5f * h;
        } else {
            const float sB = d2 / (d1 + eps);
            V0x = (x + a)        + (sB - 1.f) * a;
            V0y = (y + 0.5f * h) + (sB - 1.f) * (0.5f * h);
            V1x = x + 0.5f * w;   V1y = y + b;
            V2x = (x - a)        - (sB - 1.f) * a;
            V2y = (y - 0.5f * h) - (sB - 1.f) * (0.5f * h);
        }
        const float hre = sqrtf((V1x - V0x) * (V1x - V0x) + (V1y - V0y) * (V1y - V0y));
        const float wre = sqrtf((V2x - V1x) * (V2x - V1x) + (V2y - V1y) * (V2y - V1y));
        float theta = atan2f(V1y - V2y, V1x - V2x);
        const float PI2 = 1.5707963267948966f;
        theta = fminf(fmaxf(theta, -PI2), PI2);
        const float ct = cosf(theta), st = sinf(theta);

        const int   i  = tid / SS, j = tid % SS;
        const float tj = (float)j / 6.f - 0.5f;
        const float ti = (float)i / 6.f - 0.5f;
        const float gx = wre * scale * tj;
        const float gy = hre * scale * ti;
        const float rx =  gx * ct + gy * st + x * scale;
        const float ry = -gx * st + gy * ct + y * scale;

        const float Wf  = (float)H;
        const float inv = 1.f / (float)(H - 1);
        const float gxn = rx * scale * inv * 2.f - 1.f;
        const float gyn = ry * scale * inv * 2.f - 1.f;
        const float px = ((gxn + 1.f) * Wf - 1.f) * 0.5f;
        const float py = ((gyn + 1.f) * Wf - 1.f) * 0.5f;

        const float x0f = floorf(px), y0f = floorf(py);
        const float wx = px - x0f, wy = py - y0f;
        const int x0 = min(max((int)x0f, 0), H - 1);
        const int x1 = min(x0 + 1, H - 1);
        const int y0 = min(max((int)y0f, 0), H - 1);
        const int y1 = min(y0 + 1, H - 1);

        s_o00[tid] = y0 * H + x0;
        s_dx[tid]  = x1 - x0;            // 0 or 1
        s_dyw[tid] = (y1 - y0) * H;      // 0 or H
        s_w00[tid] = (1.f - wx) * (1.f - wy);
        s_w01[tid] = wx * (1.f - wy);
        s_w10[tid] = (1.f - wx) * wy;
        s_w11[tid] = wx * wy;
    }
    __syncthreads();

    const int warp = tid >> 5;
    const int lane = tid & 31;

    // Lane-owned points A (lane) and B (32+lane, if valid)
    const int  pA = lane;
    const bool hasB = (32 + lane) < NPTS;
    const int  pB = hasB ? 32 + lane : 0;

    // Point A constants (loop-invariant)
    const int   oA   = s_o00[pA];
    const int   dxA  = s_dx[pA];
    const int   dywA = s_dyw[pA];
    const int   bA   = oA & ~3;
    const int   iA0  = oA & 3;
    const int   iA1  = min(iA0 + dxA, 3);
    const bool  fbA  = (iA0 + dxA) > 3;        // x-pair crosses float4 window
    const int   oA01 = oA + dxA;               // absolute fallback offset (row y0)
    const float wa00 = s_w00[pA], wa01 = s_w01[pA], wa10 = s_w10[pA], wa11 = s_w11[pA];

    // Point B constants
    const int   oB   = s_o00[pB];
    const int   dxB  = s_dx[pB];
    const int   dywB = s_dyw[pB];
    const int   bB   = oB & ~3;
    const int   iB0  = oB & 3;
    const int   iB1  = min(iB0 + dxB, 3);
    const bool  fbB  = (iB0 + dxB) > 3;
    const int   oB01 = oB + dxB;
    const float wb00 = s_w00[pB], wb01 = s_w01[pB], wb10 = s_w10[pB], wb11 = s_w11[pB];

    const int cbase = half * CPER;
    const int cend  = cbase + CPER;
    #pragma unroll 1
    for (int c = cbase + warp; c < cend; c += 16) {
        const float* pl0 = base + (size_t)c * HW;
        const float* pl1 = pl0 + (size_t)8 * HW;
        float* o0 = op + c * NPTS;
        float* o1 = o0 + 8 * NPTS;

        // ---- point A, both channels: 2 rows x 2 planes = 4 x LDG.128 ----
        const float4 fA0 = __ldg((const float4*)(pl0 + bA));
        const float4 gA0 = __ldg((const float4*)(pl0 + bA + dywA));
        const float4 fA1 = __ldg((const float4*)(pl1 + bA));
        const float4 gA1 = __ldg((const float4*)(pl1 + bA + dywA));

        float vA0_01 = sel4(fA0, iA1), vA0_11 = sel4(gA0, iA1);
        float vA1_01 = sel4(fA1, iA1), vA1_11 = sel4(gA1, iA1);
        if (fbA) {
            vA0_01 = __ldg(pl0 + oA01);
            vA0_11 = __ldg(pl0 + oA01 + dywA);
            vA1_01 = __ldg(pl1 + oA01);
            vA1_11 = __ldg(pl1 + oA01 + dywA);
        }
        o0[pA] = sel4(fA0, iA0) * wa00 + vA0_01 * wa01
               + sel4(gA0, iA0) * wa10 + vA0_11 * wa11;
        o1[pA] = sel4(fA1, iA0) * wa00 + vA1_01 * wa01
               + sel4(gA1, iA0) * wa10 + vA1_11 * wa11;

        // ---- point B ----
        if (hasB) {
            const float4 fB0 = __ldg((const float4*)(pl0 + bB));
            const float4 gB0 = __ldg((const float4*)(pl0 + bB + dywB));
            const float4 fB1 = __ldg((const float4*)(pl1 + bB));
            const float4 gB1 = __ldg((const float4*)(pl1 + bB + dywB));

            float vB0_01 = sel4(fB0, iB1), vB0_11 = sel4(gB0, iB1);
            float vB1_01 = sel4(fB1, iB1), vB1_11 = sel4(gB1, iB1);
            if (fbB) {
                vB0_01 = __ldg(pl0 + oB01);
                vB0_11 = __ldg(pl0 + oB01 + dywB);
                vB1_01 = __ldg(pl1 + oB01);
                vB1_11 = __ldg(pl1 + oB01 + dywB);
            }
            o0[pB] = sel4(fB0, iB0) * wb00 + vB0_01 * wb01
                   + sel4(gB0, iB0) * wb10 + vB0_11 * wb11;
            o1[pB] = sel4(fB1, iB0) * wb00 + vB1_01 * wb01
                   + sel4(gB1, iB0) * wb10 + vB1_11 * wb11;
        }
    }
}

extern "C" void kernel_launch(void* const* d_in, const int* in_sizes, int n_in,
                              void* d_out, int out_size) {
    const float* f0 = (const float*)d_in[0];
    const float* f1 = (const float*)d_in[1];
    const float* f2 = (const float*)d_in[2];
    const float* f3 = (const float*)d_in[3];
    const float* rois = (const float*)d_in[4];
    const int* levels = (const int*)d_in[5];
    float* out = (float*)d_out;

    const int B = in_sizes[0] / (256 * 256 * 256);
    const int total = in_sizes[5];
    const int N = total / (B > 0 ? B : 1);

    oriented_roi_align_kernel<<<total * CSPLIT, 256>>>(f0, f1, f2, f3, rois, levels, out, N);
}

// round 10
// speedup vs baseline: 1.2999x; 1.2999x over previous
#include <cuda_runtime.h>
#include <math.h>

#define SS 7
#define NPTS 49
#define CCH 256
#define CSPLIT 2
#define CPER (CCH / CSPLIT)

__global__ __launch_bounds__(256) void oriented_roi_align_kernel(
    const float* __restrict__ f0, const float* __restrict__ f1,
    const float* __restrict__ f2, const float* __restrict__ f3,
    const float* __restrict__ rois, const int* __restrict__ levels,
    float* __restrict__ out, int N)
{
    const int roi  = blockIdx.x >> 1;
    const int half = blockIdx.x & 1;
    const int bb   = roi / N;
    const int tid  = threadIdx.x;

    __shared__ float s_w00[NPTS], s_w01[NPTS], s_w10[NPTS], s_w11[NPTS];
    __shared__ int   s_o00[NPTS], s_o01[NPTS], s_o10[NPTS], s_o11[NPTS];

    const int lvl = __ldg(levels + roi);
    int H; float scale; const float* fbase;
    switch (lvl) {
        case 0:  H = 256; scale = 0.25f;     fbase = f0; break;
        case 1:  H = 128; scale = 0.125f;    fbase = f1; break;
        case 2:  H = 64;  scale = 0.0625f;   fbase = f2; break;
        default: H = 32;  scale = 0.03125f;  fbase = f3; break;
    }
    const int HW = H * H;
    const float* base = fbase + (size_t)bb * CCH * HW;
    float* op = out + (size_t)roi * CCH * NPTS;

    if (tid < NPTS) {
        const float* r = rois + (size_t)roi * 6;
        const float x = r[0], y = r[1], w = r[2], h = r[3], a = r[4], b = r[5];

        // ---- parallelogram -> rectangle (matches reference) ----
        const float d1 = sqrtf(4.f * a * a + h * h);
        const float d2 = sqrtf(w * w + 4.f * b * b);
        const float eps = 1e-6f;
        float V0x, V0y, V1x, V1y, V2x, V2y;
        if (d1 > d2) {
            const float sA = d1 / (d2 + eps);
            V0x = x + a;          V0y = y + 0.5f * h;
            V1x = (x + 0.5f * w) + (sA - 1.f) * (0.5f * w);
            V1y = (y + b)        + (sA - 1.f) * b;
            V2x = x - a;          V2y = y - 0.5f * h;
        } else {
            const float sB = d2 / (d1 + eps);
            V0x = (x + a)        + (sB - 1.f) * a;
            V0y = (y + 0.5f * h) + (sB - 1.f) * (0.5f * h);
            V1x = x + 0.5f * w;   V1y = y + b;
            V2x = (x - a)        - (sB - 1.f) * a;
            V2y = (y - 0.5f * h) - (sB - 1.f) * (0.5f * h);
        }
        const float hre = sqrtf((V1x - V0x) * (V1x - V0x) + (V1y - V0y) * (V1y - V0y));
        const float wre = sqrtf((V2x - V1x) * (V2x - V1x) + (V2y - V1y) * (V2y - V1y));
        float theta = atan2f(V1y - V2y, V1x - V2x);
        const float PI2 = 1.5707963267948966f;
        theta = fminf(fmaxf(theta, -PI2), PI2);
        const float ct = cosf(theta), st = sinf(theta);

        const int   i  = tid / SS, j = tid % SS;
        const float tj = (float)j / 6.f - 0.5f;
        const float ti = (float)i / 6.f - 0.5f;
        const float gx = wre * scale * tj;
        const float gy = hre * scale * ti;
        const float rx =  gx * ct + gy * st + x * scale;
        const float ry = -gx * st + gy * ct + y * scale;

        const float Wf  = (float)H;
        const float inv = 1.f / (float)(H - 1);
        const float gxn = rx * scale * inv * 2.f - 1.f;
        const float gyn = ry * scale * inv * 2.f - 1.f;
        const float px = ((gxn + 1.f) * Wf - 1.f) * 0.5f;
        const float py = ((gyn + 1.f) * Wf - 1.f) * 0.5f;

        const float x0f = floorf(px), y0f = floorf(py);
        const float wx = px - x0f, wy = py - y0f;
        const int x0 = min(max((int)x0f, 0), H - 1);
        const int x1 = min(x0 + 1, H - 1);
        const int y0 = min(max((int)y0f, 0), H - 1);
        const int y1 = min(y0 + 1, H - 1);

        s_o00[tid] = y0 * H + x0;
        s_o01[tid] = y0 * H + x1;
        s_o10[tid] = y1 * H + x0;
        s_o11[tid] = y1 * H + x1;
        s_w00[tid] = (1.f - wx) * (1.f - wy);
        s_w01[tid] = wx * (1.f - wy);
        s_w10[tid] = (1.f - wx) * wy;
        s_w11[tid] = wx * wy;
    }
    __syncthreads();

    const int warp = tid >> 5;
    const int lane = tid & 31;

    // Register-cache the (up to) two points this lane owns.
    const int  pA = lane;
    const bool hasB = (32 + lane) < NPTS;
    const int  pB = hasB ? 32 + lane : 0;

    const int   a00 = s_o00[pA], a01 = s_o01[pA], a10 = s_o10[pA], a11 = s_o11[pA];
    const float wa00 = s_w00[pA], wa01 = s_w01[pA], wa10 = s_w10[pA], wa11 = s_w11[pA];
    const int   b00 = s_o00[pB], b01 = s_o01[pB], b10 = s_o10[pB], b11 = s_o11[pB];
    const float wb00 = s_w00[pB], wb01 = s_w01[pB], wb10 = s_w10[pB], wb11 = s_w11[pB];

    // Channel loop over this CTA's half: c = cbase + warp + 8k, unrolled x4.
    const int cbase = half * CPER;
    const int cend  = cbase + CPER;
    #pragma unroll 1
    for (int c = cbase + warp; c < cend; c += 32) {
        const float* pl0 = base + (size_t)c * HW;
        const float* pl1 = pl0 + (size_t)8 * HW;
        const float* pl2 = pl0 + (size_t)16 * HW;
        const float* pl3 = pl0 + (size_t)24 * HW;
        float* o0 = op + c * NPTS;
        float* o1 = o0 + 8 * NPTS;
        float* o2 = o0 + 16 * NPTS;
        float* o3 = o0 + 24 * NPTS;

        // ---- point A: 16 independent loads across 4 planes ----
        const float v0a00 = __ldg(pl0 + a00), v0a01 = __ldg(pl0 + a01);
        const float v0a10 = __ldg(pl0 + a10), v0a11 = __ldg(pl0 + a11);
        const float v1a00 = __ldg(pl1 + a00), v1a01 = __ldg(pl1 + a01);
        const float v1a10 = __ldg(pl1 + a10), v1a11 = __ldg(pl1 + a11);
        const float v2a00 = __ldg(pl2 + a00), v2a01 = __ldg(pl2 + a01);
        const float v2a10 = __ldg(pl2 + a10), v2a11 = __ldg(pl2 + a11);
        const float v3a00 = __ldg(pl3 + a00), v3a01 = __ldg(pl3 + a01);
        const float v3a10 = __ldg(pl3 + a10), v3a11 = __ldg(pl3 + a11);

        o0[pA] = v0a00 * wa00 + v0a01 * wa01 + v0a10 * wa10 + v0a11 * wa11;
        o1[pA] = v1a00 * wa00 + v1a01 * wa01 + v1a10 * wa10 + v1a11 * wa11;
        o2[pA] = v2a00 * wa00 + v2a01 * wa01 + v2a10 * wa10 + v2a11 * wa11;
        o3[pA] = v3a00 * wa00 + v3a01 * wa01 + v3a10 * wa10 + v3a11 * wa11;

        // ---- point B: 16 independent loads across 4 planes ----
        if (hasB) {
            const float v0b00 = __ldg(pl0 + b00), v0b01 = __ldg(pl0 + b01);
            const float v0b10 = __ldg(pl0 + b10), v0b11 = __ldg(pl0 + b11);
            const float v1b00 = __ldg(pl1 + b00), v1b01 = __ldg(pl1 + b01);
            const float v1b10 = __ldg(pl1 + b10), v1b11 = __ldg(pl1 + b11);
            const float v2b00 = __ldg(pl2 + b00), v2b01 = __ldg(pl2 + b01);
            const float v2b10 = __ldg(pl2 + b10), v2b11 = __ldg(pl2 + b11);
            const float v3b00 = __ldg(pl3 + b00), v3b01 = __ldg(pl3 + b01);
            const float v3b10 = __ldg(pl3 + b10), v3b11 = __ldg(pl3 + b11);

            o0[pB] = v0b00 * wb00 + v0b01 * wb01 + v0b10 * wb10 + v0b11 * wb11;
            o1[pB] = v1b00 * wb00 + v1b01 * wb01 + v1b10 * wb10 + v1b11 * wb11;
            o2[pB] = v2b00 * wb00 + v2b01 * wb01 + v2b10 * wb10 + v2b11 * wb11;
            o3[pB] = v3b00 * wb00 + v3b01 * wb01 + v3b10 * wb10 + v3b11 * wb11;
        }
    }
}

extern "C" void kernel_launch(void* const* d_in, const int* in_sizes, int n_in,
                              void* d_out, int out_size) {
    const float* f0 = (const float*)d_in[0];
    const float* f1 = (const float*)d_in[1];
    const float* f2 = (const float*)d_in[2];
    const float* f3 = (const float*)d_in[3];
    const float* rois = (const float*)d_in[4];
    const int* levels = (const int*)d_in[5];
    float* out = (float*)d_out;

    const int B = in_sizes[0] / (256 * 256 * 256);
    const int total = in_sizes[5];
    const int N = total / (B > 0 ? B : 1);

    oriented_roi_align_kernel<<<total * CSPLIT, 256>>>(f0, f1, f2, f3, rois, levels, out, N);
}

// round 11
// speedup vs baseline: 1.3428x; 1.0330x over previous
#include <cuda_runtime.h>
#include <math.h>

#define SS 7
#define NPTS 49
#define CCH 256
#define CHUNK 64                 // channels per work item
#define NCHUNK (CCH / CHUNK)     // 4 items per ROI

__device__ int g_item_counter;

__global__ void reset_counter_kernel() {
    g_item_counter = 0;
}

__global__ __launch_bounds__(256) void oriented_roi_align_kernel(
    const float* __restrict__ f0, const float* __restrict__ f1,
    const float* __restrict__ f2, const float* __restrict__ f3,
    const float* __restrict__ rois, const int* __restrict__ levels,
    float* __restrict__ out, int N, int total)
{
    const int tid = threadIdx.x;
    const int nItems = total * NCHUNK;

    __shared__ int   s_item;
    __shared__ float s_w00[NPTS], s_w01[NPTS], s_w10[NPTS], s_w11[NPTS];
    __shared__ int   s_o00[NPTS], s_o01[NPTS], s_o10[NPTS], s_o11[NPTS];

    const int warp = tid >> 5;
    const int lane = tid & 31;
    const int  pA = lane;
    const bool hasB = (32 + lane) < NPTS;
    const int  pB = hasB ? 32 + lane : 0;

    for (;;) {
        if (tid == 0) s_item = atomicAdd(&g_item_counter, 1);
        __syncthreads();                 // also separates prev item's smem reads
        const int item = s_item;
        if (item >= nItems) return;      // uniform across CTA

        const int roi   = item % total;  // roi-major: consecutive items mix levels
        const int chunk = item / total;
        const int bb    = roi / N;

        const int lvl = __ldg(levels + roi);
        int H; float scale; const float* fbase;
        switch (lvl) {
            case 0:  H = 256; scale = 0.25f;     fbase = f0; break;
            case 1:  H = 128; scale = 0.125f;    fbase = f1; break;
            case 2:  H = 64;  scale = 0.0625f;   fbase = f2; break;
            default: H = 32;  scale = 0.03125f;  fbase = f3; break;
        }
        const int HW = H * H;
        const float* base = fbase + (size_t)bb * CCH * HW;
        float* op = out + (size_t)roi * CCH * NPTS;

        if (tid < NPTS) {
            const float* r = rois + (size_t)roi * 6;
            const float x = r[0], y = r[1], w = r[2], h = r[3], a = r[4], b = r[5];

            // ---- parallelogram -> rectangle (matches reference) ----
            const float d1 = sqrtf(4.f * a * a + h * h);
            const float d2 = sqrtf(w * w + 4.f * b * b);
            const float eps = 1e-6f;
            float V0x, V0y, V1x, V1y, V2x, V2y;
            if (d1 > d2) {
                const float sA = d1 / (d2 + eps);
                V0x = x + a;          V0y = y + 0.5f * h;
                V1x = (x + 0.5f * w) + (sA - 1.f) * (0.5f * w);
                V1y = (y + b)        + (sA - 1.f) * b;
                V2x = x - a;          V2y = y - 0.5f * h;
            } else {
                const float sB = d2 / (d1 + eps);
                V0x = (x + a)        + (sB - 1.f) * a;
                V0y = (y + 0.5f * h) + (sB - 1.f) * (0.5f * h);
                V1x = x + 0.5f * w;   V1y = y + b;
                V2x = (x - a)        - (sB - 1.f) * a;
                V2y = (y - 0.5f * h) - (sB - 1.f) * (0.5f * h);
            }
            const float hre = sqrtf((V1x - V0x) * (V1x - V0x) + (V1y - V0y) * (V1y - V0y));
            const float wre = sqrtf((V2x - V1x) * (V2x - V1x) + (V2y - V1y) * (V2y - V1y));
            float theta = atan2f(V1y - V2y, V1x - V2x);
            const float PI2 = 1.5707963267948966f;
            theta = fminf(fmaxf(theta, -PI2), PI2);
            const float ct = cosf(theta), st = sinf(theta);

            const int   i  = tid / SS, j = tid % SS;
            const float tj = (float)j / 6.f - 0.5f;
            const float ti = (float)i / 6.f - 0.5f;
            const float gx = wre * scale * tj;
            const float gy = hre * scale * ti;
            const float rx =  gx * ct + gy * st + x * scale;
            const float ry = -gx * st + gy * ct + y * scale;

            const float Wf  = (float)H;
            const float inv = 1.f / (float)(H - 1);
            const float gxn = rx * scale * inv * 2.f - 1.f;
            const float gyn = ry * scale * inv * 2.f - 1.f;
            const float px = ((gxn + 1.f) * Wf - 1.f) * 0.5f;
            const float py = ((gyn + 1.f) * Wf - 1.f) * 0.5f;

            const float x0f = floorf(px), y0f = floorf(py);
            const float wx = px - x0f, wy = py - y0f;
            const int x0 = min(max((int)x0f, 0), H - 1);
            const int x1 = min(x0 + 1, H - 1);
            const int y0 = min(max((int)y0f, 0), H - 1);
            const int y1 = min(y0 + 1, H - 1);

            s_o00[tid] = y0 * H + x0;
            s_o01[tid] = y0 * H + x1;
            s_o10[tid] = y1 * H + x0;
            s_o11[tid] = y1 * H + x1;
            s_w00[tid] = (1.f - wx) * (1.f - wy);
            s_w01[tid] = wx * (1.f - wy);
            s_w10[tid] = (1.f - wx) * wy;
            s_w11[tid] = wx * wy;
        }
        __syncthreads();

        // Register-cache taps for this item.
        const int   a00 = s_o00[pA], a01 = s_o01[pA], a10 = s_o10[pA], a11 = s_o11[pA];
        const float wa00 = s_w00[pA], wa01 = s_w01[pA], wa10 = s_w10[pA], wa11 = s_w11[pA];
        const int   b00 = s_o00[pB], b01 = s_o01[pB], b10 = s_o10[pB], b11 = s_o11[pB];
        const float wb00 = s_w00[pB], wb01 = s_w01[pB], wb10 = s_w10[pB], wb11 = s_w11[pB];

        const int cbase = chunk * CHUNK;
        const int cend  = cbase + CHUNK;
        #pragma unroll 1
        for (int c = cbase + warp; c < cend; c += 16) {
            const float* pl0 = base + (size_t)c * HW;
            const float* pl1 = pl0 + (size_t)8 * HW;
            float* o0 = op + c * NPTS;
            float* o1 = o0 + 8 * NPTS;

            const float v0a00 = __ldg(pl0 + a00), v0a01 = __ldg(pl0 + a01);
            const float v0a10 = __ldg(pl0 + a10), v0a11 = __ldg(pl0 + a11);
            const float v1a00 = __ldg(pl1 + a00), v1a01 = __ldg(pl1 + a01);
            const float v1a10 = __ldg(pl1 + a10), v1a11 = __ldg(pl1 + a11);

            float v0b00 = 0.f, v0b01 = 0.f, v0b10 = 0.f, v0b11 = 0.f;
            float v1b00 = 0.f, v1b01 = 0.f, v1b10 = 0.f, v1b11 = 0.f;
            if (hasB) {
                v0b00 = __ldg(pl0 + b00); v0b01 = __ldg(pl0 + b01);
                v0b10 = __ldg(pl0 + b10); v0b11 = __ldg(pl0 + b11);
                v1b00 = __ldg(pl1 + b00); v1b01 = __ldg(pl1 + b01);
                v1b10 = __ldg(pl1 + b10); v1b11 = __ldg(pl1 + b11);
            }

            o0[pA] = v0a00 * wa00 + v0a01 * wa01 + v0a10 * wa10 + v0a11 * wa11;
            o1[pA] = v1a00 * wa00 + v1a01 * wa01 + v1a10 * wa10 + v1a11 * wa11;
            if (hasB) {
                o0[pB] = v0b00 * wb00 + v0b01 * wb01 + v0b10 * wb10 + v0b11 * wb11;
                o1[pB] = v1b00 * wb00 + v1b01 * wb01 + v1b10 * wb10 + v1b11 * wb11;
            }
        }
        // loop back: sync at top separates smem reuse
    }
}

extern "C" void kernel_launch(void* const* d_in, const int* in_sizes, int n_in,
                              void* d_out, int out_size) {
    const float* f0 = (const float*)d_in[0];
    const float* f1 = (const float*)d_in[1];
    const float* f2 = (const float*)d_in[2];
    const float* f3 = (const float*)d_in[3];
    const float* rois = (const float*)d_in[4];
    const int* levels = (const int*)d_in[5];
    float* out = (float*)d_out;

    const int B = in_sizes[0] / (256 * 256 * 256);
    const int total = in_sizes[5];
    const int N = total / (B > 0 ? B : 1);

    reset_counter_kernel<<<1, 1>>>();
    oriented_roi_align_kernel<<<888, 256>>>(f0, f1, f2, f3, rois, levels, out, N, total);
}

// round 12
// speedup vs baseline: 1.4121x; 1.0516x over previous
#include <cuda_runtime.h>
#include <math.h>

#define SS 7
#define NPTS 49
#define CCH 256
#define CSPLIT 2
#define CPER (CCH / CSPLIT)

__global__ __launch_bounds__(256) void oriented_roi_align_kernel(
    const float* __restrict__ f0, const float* __restrict__ f1,
    const float* __restrict__ f2, const float* __restrict__ f3,
    const float* __restrict__ rois, const int* __restrict__ levels,
    float* __restrict__ out, int N, int total)
{
    // Interleaved mapping: consecutive CTAs -> consecutive ROIs (uniform level mix per wave)
    const int bid  = blockIdx.x;
    const int roi  = bid % total;
    const int half = bid / total;
    const int bb   = roi / N;
    const int tid  = threadIdx.x;

    __shared__ float s_w00[NPTS], s_w01[NPTS], s_w10[NPTS], s_w11[NPTS];
    __shared__ int   s_o00[NPTS], s_o01[NPTS], s_o10[NPTS], s_o11[NPTS];

    const int lvl = __ldg(levels + roi);
    int H; float scale; const float* fbase;
    switch (lvl) {
        case 0:  H = 256; scale = 0.25f;     fbase = f0; break;
        case 1:  H = 128; scale = 0.125f;    fbase = f1; break;
        case 2:  H = 64;  scale = 0.0625f;   fbase = f2; break;
        default: H = 32;  scale = 0.03125f;  fbase = f3; break;
    }
    const int HW = H * H;
    const float* base = fbase + (size_t)bb * CCH * HW;
    float* op = out + (size_t)roi * CCH * NPTS;

    if (tid < NPTS) {
        const float* r = rois + (size_t)roi * 6;
        const float x = r[0], y = r[1], w = r[2], h = r[3], a = r[4], b = r[5];

        // ---- parallelogram -> rectangle (matches reference) ----
        const float d1 = sqrtf(4.f * a * a + h * h);   // |v3 - v1|
        const float d2 = sqrtf(w * w + 4.f * b * b);   // |v4 - v2|
        const float eps = 1e-6f;
        float V0x, V0y, V1x, V1y, V2x, V2y;
        if (d1 > d2) {
            const float sA = d1 / (d2 + eps);
            V0x = x + a;          V0y = y + 0.5f * h;
            V1x = (x + 0.5f * w) + (sA - 1.f) * (0.5f * w);
            V1y = (y + b)        + (sA - 1.f) * b;
            V2x = x - a;          V2y = y - 0.5f * h;
        } else {
            const float sB = d2 / (d1 + eps);
            V0x = (x + a)        + (sB - 1.f) * a;
            V0y = (y + 0.5f * h) + (sB - 1.f) * (0.5f * h);
            V1x = x + 0.5f * w;   V1y = y + b;
            V2x = (x - a)        - (sB - 1.f) * a;
            V2y = (y - 0.5f * h) - (sB - 1.f) * (0.5f * h);
        }
        const float hre = sqrtf((V1x - V0x) * (V1x - V0x) + (V1y - V0y) * (V1y - V0y));
        const float wre = sqrtf((V2x - V1x) * (V2x - V1x) + (V2y - V1y) * (V2y - V1y));
        float theta = atan2f(V1y - V2y, V1x - V2x);
        const float PI2 = 1.5707963267948966f;
        theta = fminf(fmaxf(theta, -PI2), PI2);
        const float ct = cosf(theta), st = sinf(theta);

        // ---- sample point for this (i, j) ----
        const int   i  = tid / SS, j = tid % SS;
        const float tj = (float)j / 6.f - 0.5f;
        const float ti = (float)i / 6.f - 0.5f;
        const float gx = wre * scale * tj;
        const float gy = hre * scale * ti;
        const float rx =  gx * ct + gy * st + x * scale;
        const float ry = -gx * st + gy * ct + y * scale;

        const float Wf  = (float)H;
        const float inv = 1.f / (float)(H - 1);
        const float gxn = rx * scale * inv * 2.f - 1.f;
        const float gyn = ry * scale * inv * 2.f - 1.f;
        const float px = ((gxn + 1.f) * Wf - 1.f) * 0.5f;
        const float py = ((gyn + 1.f) * Wf - 1.f) * 0.5f;

        const float x0f = floorf(px), y0f = floorf(py);
        const float wx = px - x0f, wy = py - y0f;
        const int x0 = min(max((int)x0f, 0), H - 1);
        const int x1 = min(x0 + 1, H - 1);
        const int y0 = min(max((int)y0f, 0), H - 1);
        const int y1 = min(y0 + 1, H - 1);

        s_o00[tid] = y0 * H + x0;
        s_o01[tid] = y0 * H + x1;
        s_o10[tid] = y1 * H + x0;
        s_o11[tid] = y1 * H + x1;
        s_w00[tid] = (1.f - wx) * (1.f - wy);
        s_w01[tid] = wx * (1.f - wy);
        s_w10[tid] = (1.f - wx) * wy;
        s_w11[tid] = wx * wy;
    }
    __syncthreads();

    const int warp = tid >> 5;
    const int lane = tid & 31;

    // Register-cache the (up to) two points this lane owns.
    const int  pA = lane;
    const bool hasB = (32 + lane) < NPTS;
    const int  pB = hasB ? 32 + lane : 0;

    const int   a00 = s_o00[pA], a01 = s_o01[pA], a10 = s_o10[pA], a11 = s_o11[pA];
    const float wa00 = s_w00[pA], wa01 = s_w01[pA], wa10 = s_w10[pA], wa11 = s_w11[pA];
    const int   b00 = s_o00[pB], b01 = s_o01[pB], b10 = s_o10[pB], b11 = s_o11[pB];
    const float wb00 = s_w00[pB], wb01 = s_w01[pB], wb10 = s_w10[pB], wb11 = s_w11[pB];

    // Channel loop over this CTA's half: c = cbase + warp + 8k, unrolled x2.
    const int cbase = half * CPER;
    const int cend  = cbase + CPER;
    #pragma unroll 1
    for (int c = cbase + warp; c < cend; c += 16) {
        const float* pl0 = base + (size_t)c * HW;
        const float* pl1 = pl0 + (size_t)8 * HW;
        float* o0 = op + c * NPTS;
        float* o1 = o0 + 8 * NPTS;

        const float v0a00 = __ldg(pl0 + a00), v0a01 = __ldg(pl0 + a01);
        const float v0a10 = __ldg(pl0 + a10), v0a11 = __ldg(pl0 + a11);
        const float v1a00 = __ldg(pl1 + a00), v1a01 = __ldg(pl1 + a01);
        const float v1a10 = __ldg(pl1 + a10), v1a11 = __ldg(pl1 + a11);

        float v0b00 = 0.f, v0b01 = 0.f, v0b10 = 0.f, v0b11 = 0.f;
        float v1b00 = 0.f, v1b01 = 0.f, v1b10 = 0.f, v1b11 = 0.f;
        if (hasB) {
            v0b00 = __ldg(pl0 + b00); v0b01 = __ldg(pl0 + b01);
            v0b10 = __ldg(pl0 + b10); v0b11 = __ldg(pl0 + b11);
            v1b00 = __ldg(pl1 + b00); v1b01 = __ldg(pl1 + b01);
            v1b10 = __ldg(pl1 + b10); v1b11 = __ldg(pl1 + b11);
        }

        o0[pA] = v0a00 * wa00 + v0a01 * wa01 + v0a10 * wa10 + v0a11 * wa11;
        o1[pA] = v1a00 * wa00 + v1a01 * wa01 + v1a10 * wa10 + v1a11 * wa11;
        if (hasB) {
            o0[pB] = v0b00 * wb00 + v0b01 * wb01 + v0b10 * wb10 + v0b11 * wb11;
            o1[pB] = v1b00 * wb00 + v1b01 * wb01 + v1b10 * wb10 + v1b11 * wb11;
        }
    }
}

extern "C" void kernel_launch(void* const* d_in, const int* in_sizes, int n_in,
                              void* d_out, int out_size) {
    const float* f0 = (const float*)d_in[0];
    const float* f1 = (const float*)d_in[1];
    const float* f2 = (const float*)d_in[2];
    const float* f3 = (const float*)d_in[3];
    const float* rois = (const float*)d_in[4];
    const int* levels = (const int*)d_in[5];
    float* out = (float*)d_out;

    const int B = in_sizes[0] / (256 * 256 * 256);
    const int total = in_sizes[5];        // B*N rois
    const int N = total / (B > 0 ? B : 1);

    oriented_roi_align_kernel<<<total * CSPLIT, 256>>>(f0, f1, f2, f3, rois, levels, out, N, total);
}